// round 2
// baseline (speedup 1.0000x reference)
#include <cuda_runtime.h>

// ---------------- problem constants ----------------
#define NXg 256
#define NYg 256
#define NG  (NXg*NYg)

// tile: interior 16(x) x 32(y), halo 4 (one full RK4 step per grid barrier)
#define IXt 16
#define IYt 32
#define Hh  4
#define EXt (IXt + 2*Hh)   // 24
#define EYt (IYt + 2*Hh)   // 40
#define EXT (EXt*EYt)      // 960
#define NT  256
#define NC  4              // ext cells per thread
#define NBX (NYg/IYt)      // 8  (blockIdx.x -> y tiles)
#define NBY (NXg/IXt)      // 16 (blockIdx.y -> x tiles)
#define NCTA (NBX*NBY)     // 128 CTAs <= 148 SMs -> all co-resident
#define RELAX  100
#define TSTEPS 1024

// ---------------- device state ----------------
__device__ float g_m[2][3*NG];        // ping-pong magnetization
__device__ unsigned g_count;          // barrier arrival counter (self-resetting)
__device__ volatile unsigned g_sense; // barrier sense (even #barriers/run -> replay-safe)

// sense-reversing centralized grid barrier (one atomic per CTA)
__device__ __forceinline__ void gridbar(unsigned& lsense)
{
    __threadfence();              // publish this CTA's global writes (gpu scope)
    __syncthreads();
    if (threadIdx.x == 0) {
        unsigned s = lsense ^ 1u;
        lsense = s;
        if (atomicAdd(&g_count, 1u) == NCTA - 1u) {
            g_count = 0u;         // reset before releasing
            __threadfence();
            g_sense = s;          // release
        } else {
            while (g_sense != s) __nanosleep(32);
        }
    }
    __syncthreads();
}

__global__ void __launch_bounds__(NT, 1)
k_sim(const float* __restrict__ sig,  const float* __restrict__ Bext,
      const float* __restrict__ Msat, const float* __restrict__ src,
      const float* __restrict__ pmask, float* __restrict__ out)
{
    __shared__ float sA[3][EXT];   // stage state (stages 1,3 read)
    __shared__ float sB[3][EXT];   // stage state (stages 2,4 read)
    __shared__ float sK[3][EXT];   // torque of current stage
    __shared__ float red[NT];
    __shared__ float s_pminv;

    const int tid = threadIdx.x;
    const int gx0 = (int)blockIdx.y * IXt - Hh;
    const int gy0 = (int)blockIdx.x * IYt - Hh;

    const float MU0f    = (float)(4e-7 * 3.14159265358979323846);
    const float TWO_A   = (float)(2.0 * 3.65e-12);
    const float INV_DX2 = (float)(1.0 / (50e-9 * 50e-9));

    const double hd  = 1.7595e11 * 5e-12;         // gamma * dt
    const float c05  = (float)(0.5 * hd);
    const float cfl  = (float)hd;
    const float h6   = (float)(hd / 6.0);
    const float a_rx = 0.5f,  i_rx = (float)(1.0 / (1.0 + 0.5 * 0.5));
    const float a_rn = 0.01f, i_rn = (float)(1.0 / (1.0 + 0.01 * 0.01));

    // -------- per-slot static setup (lives in registers for all 1124 steps) --------
    int   rg[NC], em[NC], ep[NC], fm[NC], fp[NC], smax[NC];
    bool  rint[NC];
    float rBx[NC], rBy[NC], rBz[NC], rSx[NC], rSy[NC], rSz[NC];
    float rCL[NC], rDg[NC], pmw[NC], m0x[NC];
    int anyp = 0;

    #pragma unroll
    for (int k = 0; k < NC; k++) {
        int e  = tid + k*NT;
        int ex = e / EYt, ey = e - ex*EYt;
        int gx = gx0 + ex, gy = gy0 + ey;
        bool ok = (e < EXT) && gx >= 0 && gx < NXg && gy >= 0 && gy < NYg;
        int g = ok ? gx*NYg + gy : 0;
        rg[k] = g;
        // max substage (1..4) at which this ext cell is still computed:
        // a side shrinks the valid region only if that ext edge is interior to the domain
        int cap = 99;
        if (gx0 >= 0)           cap = min(cap, ex);
        if (gx0 + EXt <= NXg)   cap = min(cap, EXt - 1 - ex);
        if (gy0 >= 0)           cap = min(cap, ey);
        if (gy0 + EYt <= NYg)   cap = min(cap, EYt - 1 - ey);
        smax[k] = ok ? cap : -1;
        // Neumann BC: clamp neighbors at true domain edges (precomputed once)
        em[k] = (gx == 0)       ? e : e - EYt;
        ep[k] = (gx == NXg - 1) ? e : e + EYt;
        fm[k] = (gy == 0)       ? e : e - 1;
        fp[k] = (gy == NYg - 1) ? e : e + 1;
        rint[k] = ok && ex >= Hh && ex < Hh + IXt && ey >= Hh && ey < Hh + IYt;
        float ms = ok ? Msat[g] : 1.f;
        rCL[k] = (TWO_A / ms) * INV_DX2;
        rDg[k] = MU0f * ms;
        rBx[k] = ok ? Bext[0*NG + g] : 0.f;
        rBy[k] = ok ? Bext[1*NG + g] : 0.f;
        rBz[k] = ok ? Bext[2*NG + g] : 0.f;
        rSx[k] = ok ? src [0*NG + g] : 0.f;
        rSy[k] = ok ? src [1*NG + g] : 0.f;
        rSz[k] = ok ? src [2*NG + g] : 0.f;
        float pv = rint[k] ? pmask[g] : 0.f;
        pmw[k] = pv * ms;
        m0x[k] = 0.f;
        if (pv != 0.f) anyp = 1;
    }

    // zero output (one CTA; visible to probe atomics after >=1 barrier)
    if (blockIdx.x == 0 && blockIdx.y == 0)
        for (int i = tid; i < TSTEPS; i += NT) out[i] = 0.f;

    // 1/sum(probe_mask): computed only by CTAs that own probe cells
    const int hasp = __syncthreads_or(anyp);
    if (hasp) {
        float s = 0.f;
        for (int i = tid; i < NG; i += NT) s += pmask[i];
        red[tid] = s; __syncthreads();
        for (int o = NT/2; o; o >>= 1) { if (tid < o) red[tid] += red[tid+o]; __syncthreads(); }
        if (tid == 0) s_pminv = 1.f / red[0];
    }
    __syncthreads();

    unsigned lsense = 0;

    // ================= main time loop: 100 relax + 1024 driven steps =================
    for (int step = 0; step < RELAX + TSTEPS; ++step) {
        const bool  probe = (step >= RELAX);
        const float sv    = probe ? __ldg(&sig[step - RELAX]) : 0.f;
        const float alpha = probe ? a_rn : a_rx;
        const float inv1a = probe ? i_rn : i_rx;
        const float* __restrict__ m_in  = g_m[(step + 1) & 1];
        float*       __restrict__ m_out = g_m[step & 1];

        float rM0[NC], rM1[NC], rM2[NC], a0[NC], a1[NC], a2[NC];
        float tBx[NC], tBy[NC], tBz[NC];

        #pragma unroll
        for (int k = 0; k < NC; k++) {
            float mx, my, mz;
            if (step == 0) { mx = 0.f; my = 0.f; mz = 1.f; }   // initial m = zhat
            else {
                mx = __ldcg(&m_in[0*NG + rg[k]]);   // .cg: bypass possibly-stale L1
                my = __ldcg(&m_in[1*NG + rg[k]]);
                mz = __ldcg(&m_in[2*NG + rg[k]]);
            }
            rM0[k] = mx; rM1[k] = my; rM2[k] = mz;
            a0[k] = a1[k] = a2[k] = 0.f;
            tBx[k] = fmaf(sv, rSx[k], rBx[k]);
            tBy[k] = fmaf(sv, rSy[k], rBy[k]);
            tBz[k] = fmaf(sv, rSz[k], rBz[k]);
            if (smax[k] >= 0) {
                int e = tid + k*NT;
                sA[0][e] = mx; sA[1][e] = my; sA[2][e] = mz;
            }
        }
        __syncthreads();

        // torque from state buffer S into sK (own slot: no sync needed before update)
        auto torque = [&](int s, float (*S)[EXT]) {
            #pragma unroll
            for (int k = 0; k < NC; k++) {
                if (smax[k] < s) continue;
                int e = tid + k*NT;
                float mx = S[0][e], my = S[1][e], mz = S[2][e];
                float l0 = S[0][em[k]] + S[0][ep[k]] + S[0][fm[k]] + S[0][fp[k]] - 4.f*mx;
                float l1 = S[1][em[k]] + S[1][ep[k]] + S[1][fm[k]] + S[1][fp[k]] - 4.f*my;
                float l2 = S[2][em[k]] + S[2][ep[k]] + S[2][fm[k]] + S[2][fp[k]] - 4.f*mz;
                float Bx = fmaf(rCL[k], l0, tBx[k]);
                float By = fmaf(rCL[k], l1, tBy[k]);
                float Bz = fmaf(rCL[k], l2, tBz[k]) - rDg[k]*mz;
                float px = my*Bz - mz*By;
                float py = mz*Bx - mx*Bz;
                float pz = mx*By - my*Bx;
                float qx = my*pz - mz*py;
                float qy = mz*px - mx*pz;
                float qz = mx*py - my*px;
                sK[0][e] = -(px + alpha*qx) * inv1a;
                sK[1][e] = -(py + alpha*qy) * inv1a;
                sK[2][e] = -(pz + alpha*qz) * inv1a;
            }
        };
        // accumulate + build next stage state in D (own slot reads from sK)
        auto update = [&](int s, float coef, float w, float (*D)[EXT]) {
            #pragma unroll
            for (int k = 0; k < NC; k++) {
                if (smax[k] < s) continue;
                int e = tid + k*NT;
                float k0 = sK[0][e], k1 = sK[1][e], k2 = sK[2][e];
                if (rint[k]) {
                    a0[k] = fmaf(w, k0, a0[k]);
                    a1[k] = fmaf(w, k1, a1[k]);
                    a2[k] = fmaf(w, k2, a2[k]);
                }
                D[0][e] = fmaf(coef, k0, rM0[k]);
                D[1][e] = fmaf(coef, k1, rM1[k]);
                D[2][e] = fmaf(coef, k2, rM2[k]);
            }
        };

        torque(1, sA); update(1, c05, 1.f, sB); __syncthreads();
        torque(2, sB); update(2, c05, 2.f, sA); __syncthreads();
        torque(3, sA); update(3, cfl, 2.f, sB); __syncthreads();
        torque(4, sB);  // k4 left in sK (own slots)

        // -------- final state write + probe --------
        float part = 0.f;
        #pragma unroll
        for (int k = 0; k < NC; k++) {
            if (!rint[k]) continue;
            int e = tid + k*NT;
            float v0 = rM0[k] + h6 * (a0[k] + sK[0][e]);
            float v1 = rM1[k] + h6 * (a1[k] + sK[1][e]);
            float v2 = rM2[k] + h6 * (a2[k] + sK[2][e]);
            int g = rg[k];
            __stcg(&m_out[0*NG + g], v0);
            __stcg(&m_out[1*NG + g], v1);
            __stcg(&m_out[2*NG + g], v2);
            if (step == RELAX - 1) m0x[k] = v0;          // relaxed reference state (x)
            if (probe) part += (v0 - m0x[k]) * pmw[k];   // (m - m0)*Msat*probe_mask
        }

        if (probe && hasp) {
            red[tid] = part; __syncthreads();
            for (int o = NT/2; o; o >>= 1) { if (tid < o) red[tid] += red[tid+o]; __syncthreads(); }
            if (tid == 0) atomicAdd(&out[step - RELAX], red[0] * s_pminv);
        }

        gridbar(lsense);   // 1124 barriers total (even -> sense replay-safe)
    }
}

// ---------------- host launcher: ONE graph node ----------------
extern "C" void kernel_launch(void* const* d_in, const int* in_sizes, int n_in,
                              void* d_out, int out_size)
{
    const float* sig   = (const float*)d_in[0];  // (1,T,1)
    const float* Bext  = (const float*)d_in[1];  // (1,3,256,256)
    const float* Msat  = (const float*)d_in[2];  // (1,1,256,256)
    const float* src   = (const float*)d_in[3];  // (1,3,256,256)
    const float* pmask = (const float*)d_in[4];  // (256,256)
    float* out = (float*)d_out;                  // (1,1024)

    dim3 grid(NBX, NBY);  // 8 x 16 = 128 CTAs, all co-resident on 148 SMs
    k_sim<<<grid, NT>>>(sig, Bext, Msat, src, pmask, out);
}

// round 3
// speedup vs baseline: 1.0668x; 1.0668x over previous
#include <cuda_runtime.h>

// ---------------- problem constants ----------------
#define NXg 256
#define NYg 256
#define NG  (NXg*NYg)

// tile: interior 16(x) x 32(y), halo 4 (one full RK4 step per grid barrier)
#define IXt 16
#define IYt 32
#define Hh  4
#define EXt (IXt + 2*Hh)   // 24
#define EYt (IYt + 2*Hh)   // 40
#define EXT (EXt*EYt)      // 960
#define NT  512
#define NC  2              // ext cells per thread (slot1 partially inactive)
#define NBX (NYg/IYt)      // 8
#define NBY (NXg/IXt)      // 16
#define NCTA (NBX*NBY)     // 128 CTAs <= 148 SMs -> co-resident
#define RELAX  100
#define TSTEPS 1024

// ---------------- device state ----------------
__device__ float g_m[2][3*NG];   // ping-pong exchange-ring state
__device__ unsigned g_count;     // barrier arrival counter (self-resetting)
__device__ unsigned g_sense;     // barrier sense (even flips/run -> replay-safe)

// grid barrier: release-arrive, acquire-spin (no sc-fence, no nanosleep)
__device__ __forceinline__ void gridbar(unsigned& lsense)
{
    __syncthreads();
    if (threadIdx.x == 0) {
        unsigned s = lsense ^ 1u;
        lsense = s;
        unsigned old;
        asm volatile("atom.add.acq_rel.gpu.u32 %0, [%1], 1;"
                     : "=r"(old) : "l"(&g_count) : "memory");
        if (old == NCTA - 1u) {
            asm volatile("st.relaxed.gpu.u32 [%0], %1;" :: "l"(&g_count), "r"(0u) : "memory");
            asm volatile("st.release.gpu.u32 [%0], %1;" :: "l"(&g_sense), "r"(s) : "memory");
        } else {
            unsigned v;
            do {
                asm volatile("ld.acquire.gpu.u32 %0, [%1];" : "=r"(v) : "l"(&g_sense) : "memory");
            } while (v != s);
        }
    }
    __syncthreads();
}

__global__ void __launch_bounds__(NT, 1)
k_sim(const float* __restrict__ sig,  const float* __restrict__ Bext,
      const float* __restrict__ Msat, const float* __restrict__ src,
      const float* __restrict__ pmask, float* __restrict__ out)
{
    __shared__ float sA[3][EXT];
    __shared__ float sB[3][EXT];
    __shared__ float sK[3][EXT];
    __shared__ float red[NT/32];
    __shared__ float s_pminv;
    __shared__ float s_sig[TSTEPS];

    const int tid = threadIdx.x;
    const int gx0 = (int)blockIdx.y * IXt - Hh;
    const int gy0 = (int)blockIdx.x * IYt - Hh;

    const float MU0f    = (float)(4e-7 * 3.14159265358979323846);
    const float TWO_A   = (float)(2.0 * 3.65e-12);
    const float INV_DX2 = (float)(1.0 / (50e-9 * 50e-9));

    const double hd  = 1.7595e11 * 5e-12;          // gamma*dt
    const float c05  = (float)(0.5 * hd);
    const float cfl  = (float)hd;
    const float h6   = (float)(hd / 6.0);
    const float a_rx = 0.5f,  i_rx = (float)(1.0 / (1.0 + 0.5 * 0.5));
    const float a_rn = 0.01f, i_rn = (float)(1.0 / (1.0 + 0.01 * 0.01));

    // -------- per-slot static setup (register-resident for all 1124 steps) --------
    int   rg[NC], em[NC], ep[NC], fm[NC], fp[NC];
    bool  rin[NC], rint[NC], rst[NC];
    float rBx[NC], rBy[NC], rBz[NC], rSx[NC], rSy[NC], rSz[NC];
    float rCL[NC], rDg[NC], pmw[NC], m0x[NC];
    float vM0[NC], vM1[NC], vM2[NC];   // interior m carried in registers
    int anyp = 0;

    #pragma unroll
    for (int k = 0; k < NC; k++) {
        int e  = tid + k*NT;
        bool live = (e < EXT);
        int ee = live ? e : 0;
        int ex = ee / EYt, ey = ee - ex*EYt;
        int gx = gx0 + ex, gy = gy0 + ey;
        bool ok = live && gx >= 0 && gx < NXg && gy >= 0 && gy < NYg;
        int g = ok ? gx*NYg + gy : 0;
        rg[k]  = g;
        rin[k] = ok;
        // neighbor slots: clamp at ext edge OR true domain edge (Neumann)
        em[k] = (ex == 0      || gx <= 0)        ? ee : ee - EYt;
        ep[k] = (ex == EXt-1  || gx >= NXg - 1)  ? ee : ee + EYt;
        fm[k] = (ey == 0      || gy <= 0)        ? ee : ee - 1;
        fp[k] = (ey == EYt-1  || gy >= NYg - 1)  ? ee : ee + 1;
        bool interior = ok && ex >= Hh && ex < Hh + IXt && ey >= Hh && ey < Hh + IYt;
        rint[k] = interior;
        // store only the 4-wide exchange ring of the interior
        rst[k] = interior && (ex < Hh + 4 || ex >= Hh + IXt - 4 ||
                              ey < Hh + 4 || ey >= Hh + IYt - 4);
        float ms = ok ? Msat[g] : 1.f;
        rCL[k] = (TWO_A / ms) * INV_DX2;
        rDg[k] = MU0f * ms;
        rBx[k] = ok ? Bext[0*NG + g] : 0.f;
        rBy[k] = ok ? Bext[1*NG + g] : 0.f;
        rBz[k] = ok ? Bext[2*NG + g] : 0.f;
        rSx[k] = ok ? src [0*NG + g] : 0.f;
        rSy[k] = ok ? src [1*NG + g] : 0.f;
        rSz[k] = ok ? src [2*NG + g] : 0.f;
        float pv = interior ? pmask[g] : 0.f;
        pmw[k] = pv * ms;
        m0x[k] = 0.f;
        vM0[k] = 0.f; vM1[k] = 0.f; vM2[k] = 1.f;   // initial m = zhat
        if (pv != 0.f) anyp = 1;
    }

    // signal to smem (broadcast scalar per driven step)
    for (int i = tid; i < TSTEPS; i += NT) s_sig[i] = sig[i];

    // zero output (one CTA; published by its first barrier release)
    if (blockIdx.x == 0 && blockIdx.y == 0)
        for (int i = tid; i < TSTEPS; i += NT) out[i] = 0.f;

    // 1/sum(probe_mask), only on probe-owning CTAs
    const int hasp = __syncthreads_or(anyp);
    if (hasp) {
        float s = 0.f;
        for (int i = tid; i < NG; i += NT) s += pmask[i];
        #pragma unroll
        for (int o = 16; o; o >>= 1) s += __shfl_down_sync(0xffffffffu, s, o);
        if ((tid & 31) == 0) red[tid >> 5] = s;
        __syncthreads();
        if (tid < 32) {
            float v = (tid < NT/32) ? red[tid] : 0.f;
            #pragma unroll
            for (int o = 8; o; o >>= 1) v += __shfl_down_sync(0xffffffffu, v, o);
            if (tid == 0) s_pminv = 1.f / v;
        }
    }
    __syncthreads();

    unsigned lsense = 0;

    // ================= 100 relax + 1024 driven RK4 steps =================
    for (int step = 0; step < RELAX + TSTEPS; ++step) {
        const bool  probe = (step >= RELAX);
        const float sv    = probe ? s_sig[step - RELAX] : 0.f;
        const float alpha = probe ? a_rn : a_rx;
        const float inv1a = probe ? i_rn : i_rx;
        const float* __restrict__ m_in  = g_m[(step + 1) & 1];
        float*       __restrict__ m_out = g_m[step & 1];

        float rM0[NC], rM1[NC], rM2[NC], a0[NC], a1[NC], a2[NC];
        float tBx[NC], tBy[NC], tBz[NC];

        #pragma unroll
        for (int k = 0; k < NC; k++) {
            int e = tid + k*NT;
            if (k > 0 && e >= EXT) continue;
            float mx, my, mz;
            if (rint[k]) {                       // own interior: registers
                mx = vM0[k]; my = vM1[k]; mz = vM2[k];
            } else if (rin[k] && step > 0) {     // halo: L2 (bypass stale L1)
                mx = __ldcg(&m_in[0*NG + rg[k]]);
                my = __ldcg(&m_in[1*NG + rg[k]]);
                mz = __ldcg(&m_in[2*NG + rg[k]]);
            } else {
                mx = 0.f; my = 0.f; mz = 1.f;
            }
            rM0[k] = mx; rM1[k] = my; rM2[k] = mz;
            a0[k] = a1[k] = a2[k] = 0.f;
            tBx[k] = fmaf(sv, rSx[k], rBx[k]);
            tBy[k] = fmaf(sv, rSy[k], rBy[k]);
            tBz[k] = fmaf(sv, rSz[k], rBz[k]);
            sA[0][e] = mx; sA[1][e] = my; sA[2][e] = mz;
        }
        __syncthreads();

        // torque from S into sK (unpredicated: outer-ring garbage never read live)
        auto torque = [&](float (*__restrict__ S)[EXT]) {
            #pragma unroll
            for (int k = 0; k < NC; k++) {
                int e = tid + k*NT;
                if (k > 0 && e >= EXT) continue;
                float mx = S[0][e], my = S[1][e], mz = S[2][e];
                float l0 = S[0][em[k]] + S[0][ep[k]] + S[0][fm[k]] + S[0][fp[k]] - 4.f*mx;
                float l1 = S[1][em[k]] + S[1][ep[k]] + S[1][fm[k]] + S[1][fp[k]] - 4.f*my;
                float l2 = S[2][em[k]] + S[2][ep[k]] + S[2][fm[k]] + S[2][fp[k]] - 4.f*mz;
                float Bx = fmaf(rCL[k], l0, tBx[k]);
                float By = fmaf(rCL[k], l1, tBy[k]);
                float Bz = fmaf(rCL[k], l2, tBz[k]) - rDg[k]*mz;
                float px = my*Bz - mz*By;
                float py = mz*Bx - mx*Bz;
                float pz = mx*By - my*Bx;
                float qx = my*pz - mz*py;
                float qy = mz*px - mx*pz;
                float qz = mx*py - my*px;
                sK[0][e] = -(px + alpha*qx) * inv1a;
                sK[1][e] = -(py + alpha*qy) * inv1a;
                sK[2][e] = -(pz + alpha*qz) * inv1a;
            }
        };
        auto update = [&](float coef, float w, float (*__restrict__ D)[EXT]) {
            #pragma unroll
            for (int k = 0; k < NC; k++) {
                int e = tid + k*NT;
                if (k > 0 && e >= EXT) continue;
                float k0 = sK[0][e], k1 = sK[1][e], k2 = sK[2][e];
                a0[k] = fmaf(w, k0, a0[k]);
                a1[k] = fmaf(w, k1, a1[k]);
                a2[k] = fmaf(w, k2, a2[k]);
                D[0][e] = fmaf(coef, k0, rM0[k]);
                D[1][e] = fmaf(coef, k1, rM1[k]);
                D[2][e] = fmaf(coef, k2, rM2[k]);
            }
        };

        torque(sA); update(c05, 1.f, sB); __syncthreads();
        torque(sB); update(c05, 2.f, sA); __syncthreads();
        torque(sA); update(cfl, 2.f, sB); __syncthreads();
        torque(sB);   // k4 left in sK (own slots, no sync needed)

        // -------- final state + probe --------
        float part = 0.f;
        #pragma unroll
        for (int k = 0; k < NC; k++) {
            int e = tid + k*NT;
            if (k > 0 && e >= EXT) continue;
            if (!rint[k]) continue;
            float v0 = fmaf(h6, a0[k] + sK[0][e], rM0[k]);
            float v1 = fmaf(h6, a1[k] + sK[1][e], rM1[k]);
            float v2 = fmaf(h6, a2[k] + sK[2][e], rM2[k]);
            vM0[k] = v0; vM1[k] = v1; vM2[k] = v2;
            if (rst[k]) {                      // exchange ring only
                int g = rg[k];
                __stcg(&m_out[0*NG + g], v0);
                __stcg(&m_out[1*NG + g], v1);
                __stcg(&m_out[2*NG + g], v2);
            }
            if (step == RELAX - 1) m0x[k] = v0;
            if (probe) part += (v0 - m0x[k]) * pmw[k];
        }

        if (probe && hasp) {
            #pragma unroll
            for (int o = 16; o; o >>= 1) part += __shfl_down_sync(0xffffffffu, part, o);
            if ((tid & 31) == 0) red[tid >> 5] = part;
            __syncthreads();
            if (tid < 32) {
                float v = (tid < NT/32) ? red[tid] : 0.f;
                #pragma unroll
                for (int o = 8; o; o >>= 1) v += __shfl_down_sync(0xffffffffu, v, o);
                if (tid == 0) atomicAdd(&out[step - RELAX], v * s_pminv);
            }
        }

        gridbar(lsense);   // 1124 flips (even) -> sense replay-safe
    }
}

// ---------------- host launcher: ONE graph node ----------------
extern "C" void kernel_launch(void* const* d_in, const int* in_sizes, int n_in,
                              void* d_out, int out_size)
{
    const float* sig   = (const float*)d_in[0];  // (1,T,1)
    const float* Bext  = (const float*)d_in[1];  // (1,3,256,256)
    const float* Msat  = (const float*)d_in[2];  // (1,1,256,256)
    const float* src   = (const float*)d_in[3];  // (1,3,256,256)
    const float* pmask = (const float*)d_in[4];  // (256,256)
    float* out = (float*)d_out;                  // (1,1024)

    dim3 grid(NBX, NBY);  // 128 CTAs, all co-resident
    k_sim<<<grid, NT>>>(sig, Bext, Msat, src, pmask, out);
}

// round 4
// speedup vs baseline: 1.2878x; 1.2071x over previous
#include <cuda_runtime.h>

// ---------------- problem constants ----------------
#define NXg 256
#define NYg 256
#define NG  (NXg*NYg)

// tile: interior 16(x) x 32(y), halo 4 -> ext 24x40; strips of 4 in y
#define IXt 16
#define IYt 32
#define Hh  4
#define EXt 24
#define EYt 40
#define EXT (EXt*EYt)      // 960
#define NSTR (EYt/4)       // 10 strips per row
#define ACT  (EXt*NSTR)    // 240 active threads
#define NT   256
#define NBX (NYg/IYt)      // 8
#define NBY (NXg/IXt)      // 16
#define NCTA (NBX*NBY)     // 128 CTAs <= 148 SMs -> co-resident
#define RELAX  100
#define TSTEPS 1024

// ---------------- device state ----------------
__device__ float g_m[2][3*NG];   // ping-pong exchange state
__device__ unsigned g_count;
__device__ unsigned g_sense;     // even flips per run -> replay-safe

// grid barrier: release-arrive, acquire-spin
__device__ __forceinline__ void gridbar(unsigned& lsense)
{
    __syncthreads();
    if (threadIdx.x == 0) {
        unsigned s = lsense ^ 1u;
        lsense = s;
        unsigned old;
        asm volatile("atom.add.acq_rel.gpu.u32 %0, [%1], 1;"
                     : "=r"(old) : "l"(&g_count) : "memory");
        if (old == NCTA - 1u) {
            asm volatile("st.relaxed.gpu.u32 [%0], %1;" :: "l"(&g_count), "r"(0u) : "memory");
            asm volatile("st.release.gpu.u32 [%0], %1;" :: "l"(&g_sense), "r"(s) : "memory");
        } else {
            unsigned v;
            do {
                asm volatile("ld.acquire.gpu.u32 %0, [%1];" : "=r"(v) : "l"(&g_sense) : "memory");
            } while (v != s);
        }
    }
    __syncthreads();
}

__global__ void __launch_bounds__(NT, 1)
k_sim(const float* __restrict__ sig,  const float* __restrict__ Bext,
      const float* __restrict__ Msat, const float* __restrict__ src,
      const float* __restrict__ pmask, float* __restrict__ out)
{
    __shared__ __align__(16) float S0[EXT];
    __shared__ __align__(16) float S1[EXT];
    __shared__ __align__(16) float S2[EXT];
    __shared__ float red[NT/32];
    __shared__ float s_pminv;
    __shared__ float s_sig[TSTEPS];

    const int tid = threadIdx.x;
    const bool live = (tid < ACT);
    const int ex  = live ? tid / NSTR : 0;
    const int sy  = live ? tid % NSTR : 0;
    const int gx0 = (int)blockIdx.y * IXt - Hh;
    const int gy0 = (int)blockIdx.x * IYt - Hh;
    const int gx  = gx0 + ex;
    const int gyb = gy0 + 4*sy;               // strip base y (multiple of 4)
    const int e   = ex*EYt + 4*sy;            // own ext base index

    // clamped global float4 base (address-safe; garbage never read by valid cells)
    const int gxc = min(max(gx, 0), NXg - 1);
    const int gyc = min(max(gyb, 0), NYg - 4);
    const int g   = gxc*NYg + gyc;

    // neighbor rows in ext space (clamp at ext edge or true domain edge)
    const int exm = (ex == 0       || gx <= 0)        ? ex : ex - 1;
    const int exq = (ex == EXt - 1 || gx >= NXg - 1)  ? ex : ex + 1;
    const int emb = exm*EYt + 4*sy;
    const int epb = exq*EYt + 4*sy;
    // y strip-edge neighbors (domain clamp only ever hits cell 0 / cell 3)
    const int yL = (sy == 0        || gyb <= 0)           ? e     : e - 1;
    const int yR = (sy == NSTR - 1 || gyb + 3 >= NYg - 1) ? e + 3 : e + 4;

    const bool sint = live && ex >= Hh && ex < Hh + IXt && sy >= 1 && sy <= NSTR - 2;
    const bool ring = sint && (ex < Hh + 4 || ex >= Hh + IXt - 4 ||
                               sy == 1 || sy == NSTR - 2);

    const float MU0f    = (float)(4e-7 * 3.14159265358979323846);
    const float TWO_A   = (float)(2.0 * 3.65e-12);
    const float INV_DX2 = (float)(1.0 / (50e-9 * 50e-9));
    const double hd  = 1.7595e11 * 5e-12;
    const float c05  = (float)(0.5 * hd);
    const float cfl  = (float)hd;
    const float h6   = (float)(hd / 6.0);
    const float a_rx = 0.5f,  i_rx = (float)(1.0 / (1.0 + 0.5 * 0.5));
    const float a_rn = 0.01f, i_rn = (float)(1.0 / (1.0 + 0.01 * 0.01));

    // -------- static per-cell constants (registers, whole run) --------
    float rB0[4], rB1[4], rB2[4], rS0[4], rS1[4], rS2[4];
    float rCL[4], rDg[4], pmw[4], m0x[4];
    int anyp = 0;
    #pragma unroll
    for (int j = 0; j < 4; j++) {
        int gyj = gyb + j;
        bool ok = live && gx >= 0 && gx < NXg && gyj >= 0 && gyj < NYg;
        int gj = ok ? gx*NYg + gyj : g;       // clamped fallback: safe address
        float ms = Msat[gj];
        rCL[j] = (TWO_A / ms) * INV_DX2;
        rDg[j] = MU0f * ms;
        rB0[j] = Bext[0*NG + gj]; rB1[j] = Bext[1*NG + gj]; rB2[j] = Bext[2*NG + gj];
        rS0[j] = src [0*NG + gj]; rS1[j] = src [1*NG + gj]; rS2[j] = src [2*NG + gj];
        float pv = (sint && ok) ? pmask[gj] : 0.f;
        pmw[j] = pv * ms;
        m0x[j] = 0.f;
        if (pv != 0.f) anyp = 1;
    }

    for (int i = tid; i < TSTEPS; i += NT) s_sig[i] = sig[i];
    if (blockIdx.x == 0 && blockIdx.y == 0)
        for (int i = tid; i < TSTEPS; i += NT) out[i] = 0.f;

    const int hasp = __syncthreads_or(anyp);
    if (hasp) {
        float s = 0.f;
        for (int i = tid; i < NG; i += NT) s += pmask[i];
        #pragma unroll
        for (int o = 16; o; o >>= 1) s += __shfl_down_sync(0xffffffffu, s, o);
        if ((tid & 31) == 0) red[tid >> 5] = s;
        __syncthreads();
        if (tid < 32) {
            float v = (tid < NT/32) ? red[tid] : 0.f;
            #pragma unroll
            for (int o = 4; o; o >>= 1) v += __shfl_down_sync(0xffffffffu, v, o);
            if (tid == 0) s_pminv = 1.f / v;
        }
    }
    __syncthreads();

    // m carried in registers between steps (interior); mb = m at step start
    float mb0[4], mb1[4], mb2[4];
    #pragma unroll
    for (int j = 0; j < 4; j++) { mb0[j] = 0.f; mb1[j] = 0.f; mb2[j] = 1.f; }
    if (live) {   // initial state into smem for stage-1 of step 0
        *(float4*)&S0[e] = make_float4(0.f, 0.f, 0.f, 0.f);
        *(float4*)&S1[e] = make_float4(0.f, 0.f, 0.f, 0.f);
        *(float4*)&S2[e] = make_float4(1.f, 1.f, 1.f, 1.f);
    }

    unsigned lsense = 0;

    for (int step = 0; step < RELAX + TSTEPS; ++step) {
        const bool  probe = (step >= RELAX);
        const float sv    = probe ? s_sig[step - RELAX] : 0.f;
        const float alpha = probe ? a_rn : a_rx;
        const float inv1a = probe ? i_rn : i_rx;
        const float* __restrict__ m_in  = g_m[(step + 1) & 1];
        float*       __restrict__ m_out = g_m[step & 1];

        // ---- refresh halo strips from L2 (interior S/mb already valid) ----
        if (live && !sint && step > 0) {
            float4 a = __ldcg((const float4*)&m_in[0*NG + g]);
            float4 b = __ldcg((const float4*)&m_in[1*NG + g]);
            float4 c = __ldcg((const float4*)&m_in[2*NG + g]);
            mb0[0]=a.x; mb0[1]=a.y; mb0[2]=a.z; mb0[3]=a.w;
            mb1[0]=b.x; mb1[1]=b.y; mb1[2]=b.z; mb1[3]=b.w;
            mb2[0]=c.x; mb2[1]=c.y; mb2[2]=c.z; mb2[3]=c.w;
            *(float4*)&S0[e] = a; *(float4*)&S1[e] = b; *(float4*)&S2[e] = c;
        }

        float tB0[4], tB1[4], tB2[4];
        float st0[4], st1[4], st2[4];
        float a0[4], a1[4], a2[4];
        #pragma unroll
        for (int j = 0; j < 4; j++) {
            tB0[j] = fmaf(sv, rS0[j], rB0[j]);
            tB1[j] = fmaf(sv, rS1[j], rB1[j]);
            tB2[j] = fmaf(sv, rS2[j], rB2[j]);
            st0[j] = mb0[j]; st1[j] = mb1[j]; st2[j] = mb2[j];
            a0[j] = 0.f; a1[j] = 0.f; a2[j] = 0.f;
        }
        __syncthreads();

        // one RK substage: torque from (st regs + smem neighbors), accumulate,
        // build next stage state in st, optionally publish to smem
        auto stage = [&](float coef, float w, bool writeS) {
            float nm0[4], nm1[4], nm2[4], np0[4], np1[4], np2[4];
            float4 v;
            v = *(const float4*)&S0[emb]; nm0[0]=v.x; nm0[1]=v.y; nm0[2]=v.z; nm0[3]=v.w;
            v = *(const float4*)&S1[emb]; nm1[0]=v.x; nm1[1]=v.y; nm1[2]=v.z; nm1[3]=v.w;
            v = *(const float4*)&S2[emb]; nm2[0]=v.x; nm2[1]=v.y; nm2[2]=v.z; nm2[3]=v.w;
            v = *(const float4*)&S0[epb]; np0[0]=v.x; np0[1]=v.y; np0[2]=v.z; np0[3]=v.w;
            v = *(const float4*)&S1[epb]; np1[0]=v.x; np1[1]=v.y; np1[2]=v.z; np1[3]=v.w;
            v = *(const float4*)&S2[epb]; np2[0]=v.x; np2[1]=v.y; np2[2]=v.z; np2[3]=v.w;
            float lf0 = S0[yL], lf1 = S1[yL], lf2 = S2[yL];
            float rg0 = S0[yR], rg1 = S1[yR], rg2 = S2[yR];
            #pragma unroll
            for (int j = 0; j < 4; j++) {
                float mx = st0[j], my = st1[j], mz = st2[j];
                float yl0 = j ? st0[j-1] : lf0;
                float yl1 = j ? st1[j-1] : lf1;
                float yl2 = j ? st2[j-1] : lf2;
                float yr0 = (j < 3) ? st0[j+1] : rg0;
                float yr1 = (j < 3) ? st1[j+1] : rg1;
                float yr2 = (j < 3) ? st2[j+1] : rg2;
                float l0 = nm0[j] + np0[j] + yl0 + yr0 - 4.f*mx;
                float l1 = nm1[j] + np1[j] + yl1 + yr1 - 4.f*my;
                float l2 = nm2[j] + np2[j] + yl2 + yr2 - 4.f*mz;
                float Bx = fmaf(rCL[j], l0, tB0[j]);
                float By = fmaf(rCL[j], l1, tB1[j]);
                float Bz = fmaf(rCL[j], l2, tB2[j]) - rDg[j]*mz;
                float px = my*Bz - mz*By;
                float py = mz*Bx - mx*Bz;
                float pz = mx*By - my*Bx;
                float qx = my*pz - mz*py;
                float qy = mz*px - mx*pz;
                float qz = mx*py - my*px;
                float k0 = -(px + alpha*qx) * inv1a;
                float k1 = -(py + alpha*qy) * inv1a;
                float k2 = -(pz + alpha*qz) * inv1a;
                a0[j] = fmaf(w, k0, a0[j]);
                a1[j] = fmaf(w, k1, a1[j]);
                a2[j] = fmaf(w, k2, a2[j]);
                st0[j] = fmaf(coef, k0, mb0[j]);
                st1[j] = fmaf(coef, k1, mb1[j]);
                st2[j] = fmaf(coef, k2, mb2[j]);
            }
            if (writeS && live) {
                *(float4*)&S0[e] = make_float4(st0[0], st0[1], st0[2], st0[3]);
                *(float4*)&S1[e] = make_float4(st1[0], st1[1], st1[2], st1[3]);
                *(float4*)&S2[e] = make_float4(st2[0], st2[1], st2[2], st2[3]);
            }
        };

        stage(c05, 1.f, true);  __syncthreads();
        stage(c05, 2.f, true);  __syncthreads();
        stage(cfl, 2.f, true);  __syncthreads();
        stage(0.f, 1.f, false); // k4 folded into acc
        __syncthreads();        // stage-3 reads done before final S overwrite

        // ---- final m (interior), publish to smem + exchange ring to L2 ----
        float part = 0.f;
        if (sint) {
            #pragma unroll
            for (int j = 0; j < 4; j++) {
                mb0[j] = fmaf(h6, a0[j], mb0[j]);
                mb1[j] = fmaf(h6, a1[j], mb1[j]);
                mb2[j] = fmaf(h6, a2[j], mb2[j]);
                if (step == RELAX - 1) m0x[j] = mb0[j];
                if (probe) part += (mb0[j] - m0x[j]) * pmw[j];
            }
            float4 a = make_float4(mb0[0], mb0[1], mb0[2], mb0[3]);
            float4 b = make_float4(mb1[0], mb1[1], mb1[2], mb1[3]);
            float4 c = make_float4(mb2[0], mb2[1], mb2[2], mb2[3]);
            *(float4*)&S0[e] = a; *(float4*)&S1[e] = b; *(float4*)&S2[e] = c;
            if (ring) {
                __stcg((float4*)&m_out[0*NG + g], a);
                __stcg((float4*)&m_out[1*NG + g], b);
                __stcg((float4*)&m_out[2*NG + g], c);
            }
        }

        if (probe && hasp) {
            #pragma unroll
            for (int o = 16; o; o >>= 1) part += __shfl_down_sync(0xffffffffu, part, o);
            if ((tid & 31) == 0) red[tid >> 5] = part;
            __syncthreads();
            if (tid < 32) {
                float v2 = (tid < NT/32) ? red[tid] : 0.f;
                #pragma unroll
                for (int o = 4; o; o >>= 1) v2 += __shfl_down_sync(0xffffffffu, v2, o);
                if (tid == 0) atomicAdd(&out[step - RELAX], v2 * s_pminv);
            }
        }

        gridbar(lsense);
    }
}

// ---------------- host launcher: ONE graph node ----------------
extern "C" void kernel_launch(void* const* d_in, const int* in_sizes, int n_in,
                              void* d_out, int out_size)
{
    const float* sig   = (const float*)d_in[0];
    const float* Bext  = (const float*)d_in[1];
    const float* Msat  = (const float*)d_in[2];
    const float* src   = (const float*)d_in[3];
    const float* pmask = (const float*)d_in[4];
    float* out = (float*)d_out;

    dim3 grid(NBX, NBY);
    k_sim<<<grid, NT>>>(sig, Bext, Msat, src, pmask, out);
}

// round 5
// speedup vs baseline: 1.2991x; 1.0088x over previous
#include <cuda_runtime.h>

// ---------------- problem constants ----------------
#define NXg 256
#define NYg 256
#define NG  (NXg*NYg)

// tile: interior 16(x) x 32(y), halo 4 -> ext 24x40; strips of 2 in y
#define IXt 16
#define IYt 32
#define Hh  4
#define EXt 24
#define EYt 40
#define EXT (EXt*EYt)      // 960
#define SW   2             // strip width (cells per thread)
#define NSTR (EYt/SW)      // 20 strips per row
#define ACT  (EXt*NSTR)    // 480 active threads
#define NT   512
#define NBX (NYg/IYt)      // 8
#define NBY (NXg/IXt)      // 16
#define NCTA (NBX*NBY)     // 128 CTAs <= 148 SMs -> co-resident
#define RELAX  100
#define TSTEPS 1024

// ---------------- device state ----------------
__device__ float g_m[2][3*NG];   // ping-pong exchange state
__device__ unsigned g_count;
__device__ unsigned g_sense;     // even flips per run -> replay-safe

// grid barrier: release-arrive, acquire-spin
__device__ __forceinline__ void gridbar(unsigned& lsense)
{
    __syncthreads();
    if (threadIdx.x == 0) {
        unsigned s = lsense ^ 1u;
        lsense = s;
        unsigned old;
        asm volatile("atom.add.acq_rel.gpu.u32 %0, [%1], 1;"
                     : "=r"(old) : "l"(&g_count) : "memory");
        if (old == NCTA - 1u) {
            asm volatile("st.relaxed.gpu.u32 [%0], %1;" :: "l"(&g_count), "r"(0u) : "memory");
            asm volatile("st.release.gpu.u32 [%0], %1;" :: "l"(&g_sense), "r"(s) : "memory");
        } else {
            unsigned v;
            do {
                asm volatile("ld.acquire.gpu.u32 %0, [%1];" : "=r"(v) : "l"(&g_sense) : "memory");
            } while (v != s);
        }
    }
    __syncthreads();
}

__global__ void __launch_bounds__(NT, 1)
k_sim(const float* __restrict__ sig,  const float* __restrict__ Bext,
      const float* __restrict__ Msat, const float* __restrict__ src,
      const float* __restrict__ pmask, float* __restrict__ out)
{
    __shared__ __align__(16) float SA[3][EXT];   // stage ping
    __shared__ __align__(16) float SB[3][EXT];   // stage pong
    __shared__ float red[NT/32];
    __shared__ float s_pminv;
    __shared__ float s_sig[TSTEPS];

    const int tid = threadIdx.x;
    const bool live = (tid < ACT);
    const int ex  = live ? tid / NSTR : 0;
    const int sy  = live ? tid % NSTR : 0;
    const int gx0 = (int)blockIdx.y * IXt - Hh;
    const int gy0 = (int)blockIdx.x * IYt - Hh;
    const int gx  = gx0 + ex;
    const int gyb = gy0 + SW*sy;              // strip base y (even)
    const int e   = ex*EYt + SW*sy;           // own ext base index

    // clamped global base (address-safe; garbage never read by valid cells)
    const int gxc = min(max(gx, 0), NXg - 1);
    const int gyc = min(max(gyb, 0), NYg - SW);
    const int g   = gxc*NYg + gyc;

    // x-neighbor rows in ext space (clamp at ext edge or true domain edge)
    const int exm = (ex == 0       || gx <= 0)       ? ex : ex - 1;
    const int exq = (ex == EXt - 1 || gx >= NXg - 1) ? ex : ex + 1;
    const int emb = exm*EYt + SW*sy;
    const int epb = exq*EYt + SW*sy;
    // y strip-edge neighbors (domain clamp folds to strip edge cell)
    const int yL = (sy == 0        || gyb <= 0)            ? e      : e - 1;
    const int yR = (sy == NSTR - 1 || gyb + SW - 1 >= NYg - 1) ? e + SW - 1 : e + SW;

    // interior: ex in [Hh, Hh+IXt), strip fully in interior y (sy in [2, 17])
    const bool sint = live && ex >= Hh && ex < Hh + IXt && sy >= Hh/SW && sy < (Hh + IYt)/SW;
    // 4-wide exchange ring of the interior
    const bool ring = sint && (ex < Hh + 4 || ex >= Hh + IXt - 4 ||
                               sy < Hh/SW + 2 || sy >= (Hh + IYt)/SW - 2);

    const float MU0f    = (float)(4e-7 * 3.14159265358979323846);
    const float TWO_A   = (float)(2.0 * 3.65e-12);
    const float INV_DX2 = (float)(1.0 / (50e-9 * 50e-9));
    const double hd  = 1.7595e11 * 5e-12;
    const float c05  = (float)(0.5 * hd);
    const float cfl  = (float)hd;
    const float h6   = (float)(hd / 6.0);
    const float a_rx = 0.5f,  i_rx = (float)(1.0 / (1.0 + 0.5 * 0.5));
    const float a_rn = 0.01f, i_rn = (float)(1.0 / (1.0 + 0.01 * 0.01));

    // -------- static per-cell constants (registers, whole run) --------
    float rB0[SW], rB1[SW], rB2[SW], rS0[SW], rS1[SW], rS2[SW];
    float rCL[SW], rDg[SW], pmw[SW], m0x[SW];
    int anyp = 0;
    #pragma unroll
    for (int j = 0; j < SW; j++) {
        int gyj = gyb + j;
        bool ok = live && gx >= 0 && gx < NXg && gyj >= 0 && gyj < NYg;
        int gj = ok ? gx*NYg + gyj : g;
        float ms = Msat[gj];
        rCL[j] = (TWO_A / ms) * INV_DX2;
        rDg[j] = MU0f * ms;
        rB0[j] = Bext[0*NG + gj]; rB1[j] = Bext[1*NG + gj]; rB2[j] = Bext[2*NG + gj];
        rS0[j] = src [0*NG + gj]; rS1[j] = src [1*NG + gj]; rS2[j] = src [2*NG + gj];
        float pv = (sint && ok) ? pmask[gj] : 0.f;
        pmw[j] = pv * ms;
        m0x[j] = 0.f;
        if (pv != 0.f) anyp = 1;
    }

    for (int i = tid; i < TSTEPS; i += NT) s_sig[i] = sig[i];
    if (blockIdx.x == 0 && blockIdx.y == 0)
        for (int i = tid; i < TSTEPS; i += NT) out[i] = 0.f;

    const int hasp = __syncthreads_or(anyp);
    if (hasp) {
        float s = 0.f;
        for (int i = tid; i < NG; i += NT) s += pmask[i];
        #pragma unroll
        for (int o = 16; o; o >>= 1) s += __shfl_down_sync(0xffffffffu, s, o);
        if ((tid & 31) == 0) red[tid >> 5] = s;
        __syncthreads();
        if (tid < 32) {
            float v = (tid < NT/32) ? red[tid] : 0.f;
            #pragma unroll
            for (int o = 8; o; o >>= 1) v += __shfl_down_sync(0xffffffffu, v, o);
            if (tid == 0) s_pminv = 1.f / v;
        }
    }
    __syncthreads();

    // m carried in registers between steps; SA = step-start state
    float mb0[SW], mb1[SW], mb2[SW];
    #pragma unroll
    for (int j = 0; j < SW; j++) { mb0[j] = 0.f; mb1[j] = 0.f; mb2[j] = 1.f; }
    if (live) {
        *(float2*)&SA[0][e] = make_float2(0.f, 0.f);
        *(float2*)&SA[1][e] = make_float2(0.f, 0.f);
        *(float2*)&SA[2][e] = make_float2(1.f, 1.f);
    }

    unsigned lsense = 0;

    for (int step = 0; step < RELAX + TSTEPS; ++step) {
        const bool  probe = (step >= RELAX);
        const float sv    = probe ? s_sig[step - RELAX] : 0.f;
        const float alpha = probe ? a_rn : a_rx;
        const float inv1a = probe ? i_rn : i_rx;
        const float* __restrict__ m_in  = g_m[(step + 1) & 1];
        float*       __restrict__ m_out = g_m[step & 1];

        // ---- halo refresh from L2, issued first after the barrier ----
        if (live && !sint && step > 0) {
            float2 a = __ldcg((const float2*)&m_in[0*NG + g]);
            float2 b = __ldcg((const float2*)&m_in[1*NG + g]);
            float2 c = __ldcg((const float2*)&m_in[2*NG + g]);
            mb0[0]=a.x; mb0[1]=a.y;
            mb1[0]=b.x; mb1[1]=b.y;
            mb2[0]=c.x; mb2[1]=c.y;
            *(float2*)&SA[0][e] = a; *(float2*)&SA[1][e] = b; *(float2*)&SA[2][e] = c;
        }

        float tB0[SW], tB1[SW], tB2[SW];
        float st0[SW], st1[SW], st2[SW];
        float a0[SW], a1[SW], a2[SW];
        #pragma unroll
        for (int j = 0; j < SW; j++) {
            tB0[j] = fmaf(sv, rS0[j], rB0[j]);
            tB1[j] = fmaf(sv, rS1[j], rB1[j]);
            tB2[j] = fmaf(sv, rS2[j], rB2[j]);
            st0[j] = mb0[j]; st1[j] = mb1[j]; st2[j] = mb2[j];
            a0[j] = 0.f; a1[j] = 0.f; a2[j] = 0.f;
        }
        __syncthreads();

        // one RK substage: torque from (st regs + S neighbors), accumulate,
        // build next stage state in st, publish to D
        auto stage = [&](const float (*__restrict__ S)[EXT],
                         float (*__restrict__ D)[EXT],
                         float coef, float w, bool writeD) {
            float2 nm0 = *(const float2*)&S[0][emb];
            float2 nm1 = *(const float2*)&S[1][emb];
            float2 nm2 = *(const float2*)&S[2][emb];
            float2 np0 = *(const float2*)&S[0][epb];
            float2 np1 = *(const float2*)&S[1][epb];
            float2 np2 = *(const float2*)&S[2][epb];
            float lf0 = S[0][yL], lf1 = S[1][yL], lf2 = S[2][yL];
            float rg0 = S[0][yR], rg1 = S[1][yR], rg2 = S[2][yR];
            float xm0[SW] = {nm0.x, nm0.y}, xm1[SW] = {nm1.x, nm1.y}, xm2[SW] = {nm2.x, nm2.y};
            float xp0[SW] = {np0.x, np0.y}, xp1[SW] = {np1.x, np1.y}, xp2[SW] = {np2.x, np2.y};
            #pragma unroll
            for (int j = 0; j < SW; j++) {
                float mx = st0[j], my = st1[j], mz = st2[j];
                float yl0 = j ? st0[j-1] : lf0;
                float yl1 = j ? st1[j-1] : lf1;
                float yl2 = j ? st2[j-1] : lf2;
                float yr0 = (j < SW-1) ? st0[j+1] : rg0;
                float yr1 = (j < SW-1) ? st1[j+1] : rg1;
                float yr2 = (j < SW-1) ? st2[j+1] : rg2;
                float l0 = xm0[j] + xp0[j] + yl0 + yr0 - 4.f*mx;
                float l1 = xm1[j] + xp1[j] + yl1 + yr1 - 4.f*my;
                float l2 = xm2[j] + xp2[j] + yl2 + yr2 - 4.f*mz;
                float Bx = fmaf(rCL[j], l0, tB0[j]);
                float By = fmaf(rCL[j], l1, tB1[j]);
                float Bz = fmaf(rCL[j], l2, tB2[j]) - rDg[j]*mz;
                float px = my*Bz - mz*By;
                float py = mz*Bx - mx*Bz;
                float pz = mx*By - my*Bx;
                float qx = my*pz - mz*py;
                float qy = mz*px - mx*pz;
                float qz = mx*py - my*px;
                float k0 = -(px + alpha*qx) * inv1a;
                float k1 = -(py + alpha*qy) * inv1a;
                float k2 = -(pz + alpha*qz) * inv1a;
                a0[j] = fmaf(w, k0, a0[j]);
                a1[j] = fmaf(w, k1, a1[j]);
                a2[j] = fmaf(w, k2, a2[j]);
                st0[j] = fmaf(coef, k0, mb0[j]);
                st1[j] = fmaf(coef, k1, mb1[j]);
                st2[j] = fmaf(coef, k2, mb2[j]);
            }
            if (writeD && live) {
                *(float2*)&D[0][e] = make_float2(st0[0], st0[1]);
                *(float2*)&D[1][e] = make_float2(st1[0], st1[1]);
                *(float2*)&D[2][e] = make_float2(st2[0], st2[1]);
            }
        };

        stage(SA, SB, c05, 1.f, true); __syncthreads();
        stage(SB, SA, c05, 2.f, true); __syncthreads();
        stage(SA, SB, cfl, 2.f, true); __syncthreads();
        stage(SB, SA, 0.f, 1.f, false);   // k4 folded into acc; no publish

        // ---- final m (interior): SA publish + exchange ring to L2 ----
        float part = 0.f;
        if (sint) {
            #pragma unroll
            for (int j = 0; j < SW; j++) {
                mb0[j] = fmaf(h6, a0[j], mb0[j]);
                mb1[j] = fmaf(h6, a1[j], mb1[j]);
                mb2[j] = fmaf(h6, a2[j], mb2[j]);
                if (step == RELAX - 1) m0x[j] = mb0[j];
                if (probe) part += (mb0[j] - m0x[j]) * pmw[j];
            }
            float2 a = make_float2(mb0[0], mb0[1]);
            float2 b = make_float2(mb1[0], mb1[1]);
            float2 c = make_float2(mb2[0], mb2[1]);
            // stage-4 reads SB; writing SA here races only with next-step reads,
            // which are separated by gridbar's trailing __syncthreads
            *(float2*)&SA[0][e] = a; *(float2*)&SA[1][e] = b; *(float2*)&SA[2][e] = c;
            if (ring) {
                __stcg((float2*)&m_out[0*NG + g], a);
                __stcg((float2*)&m_out[1*NG + g], b);
                __stcg((float2*)&m_out[2*NG + g], c);
            }
        }

        if (probe && hasp) {
            #pragma unroll
            for (int o = 16; o; o >>= 1) part += __shfl_down_sync(0xffffffffu, part, o);
            if ((tid & 31) == 0) red[tid >> 5] = part;
            __syncthreads();
            if (tid < 32) {
                float v2 = (tid < NT/32) ? red[tid] : 0.f;
                #pragma unroll
                for (int o = 8; o; o >>= 1) v2 += __shfl_down_sync(0xffffffffu, v2, o);
                if (tid == 0) atomicAdd(&out[step - RELAX], v2 * s_pminv);
            }
        }

        gridbar(lsense);
    }
}

// ---------------- host launcher: ONE graph node ----------------
extern "C" void kernel_launch(void* const* d_in, const int* in_sizes, int n_in,
                              void* d_out, int out_size)
{
    const float* sig   = (const float*)d_in[0];
    const float* Bext  = (const float*)d_in[1];
    const float* Msat  = (const float*)d_in[2];
    const float* src   = (const float*)d_in[3];
    const float* pmask = (const float*)d_in[4];
    float* out = (float*)d_out;

    dim3 grid(NBX, NBY);
    k_sim<<<grid, NT>>>(sig, Bext, Msat, src, pmask, out);
}